// round 2
// baseline (speedup 1.0000x reference)
#include <cuda_runtime.h>

#define EDGES 200000
#define ROWSZ 400000
#define CDIM  128
#define NPAD  50048      // 391*128, padded node count

// ---------------- scratch (static device allocations) ----------------
__device__ float g_S[NPAD * CDIM];          // segment sum of x
__device__ float g_T[NPAD * CDIM];          // segment sum of pair sums
__device__ int   g_deg[NPAD];               // rows per node
__device__ float g_Z[NPAD * 256];           // [deg*S, (deg-1)*S + T]
__device__ float g_P[NPAD * 256];           // S @ Bw
__device__ float g_Q[NPAD * 256];           // Z @ Cw
__device__ float g_Y[102400000];            // pre-BN1 activations [2E, 256]
__device__ float g_A[CDIM * 256];           // W0 + Wm2
__device__ float g_Bw[CDIM * 256];          // Wm1 + Wm2
__device__ float g_Cw[256 * 256];           // Wl + Wm
__device__ float g_stat1[512];              // col sum / sumsq of Y
__device__ float g_stat2[256];              // col sum / sumsq of pre-BN2
__device__ float g_sc1[256], g_sh1[256];
__device__ float g_sc2[128], g_sh2[128];

// ---------------- weight folding ----------------
__global__ void prep_w(const float* __restrict__ w1) {
    int idx = blockIdx.x * blockDim.x + threadIdx.x;   // 65536
    int k = idx >> 8;
    int j = idx & 255;
    g_Cw[idx] = w1[(128 + k) * 256 + j] + w1[(384 + k) * 256 + j];
    if (k < 128) {
        g_A[idx]  = w1[k * 256 + j]         + w1[(512 + k) * 256 + j];
        g_Bw[idx] = w1[(384 + k) * 256 + j] + w1[(512 + k) * 256 + j];
    }
}

// ---------------- per-edge segment accumulation ----------------
__global__ void edge_accum(const float* __restrict__ x, const int* __restrict__ ei) {
    int gw   = (blockIdx.x * blockDim.x + threadIdx.x) >> 5;
    int lane = threadIdx.x & 31;
    if (gw >= EDGES) return;
    int n0 = ei[2 * gw], n1 = ei[2 * gw + 1];
    const float4* x4 = (const float4*)x;
    float4 a = x4[(size_t)(2 * gw) * 32 + lane];
    float4 b = x4[(size_t)(2 * gw) * 32 + 32 + lane];
    float4 p = make_float4(a.x + b.x, a.y + b.y, a.z + b.z, a.w + b.w);
    atomicAdd((float4*)&g_S[(size_t)n0 * CDIM + lane * 4], a);
    atomicAdd((float4*)&g_S[(size_t)n1 * CDIM + lane * 4], b);
    atomicAdd((float4*)&g_T[(size_t)n0 * CDIM + lane * 4], p);
    atomicAdd((float4*)&g_T[(size_t)n1 * CDIM + lane * 4], p);
    if (lane == 0) { atomicAdd(&g_deg[n0], 1); atomicAdd(&g_deg[n1], 1); }
}

// ---------------- build Z = [deg*S, (deg-1)*S + T] ----------------
__global__ void build_Z() {
    int idx = blockIdx.x * blockDim.x + threadIdx.x;   // NPAD*128
    int n = idx >> 7, c = idx & 127;
    float s  = g_S[idx];
    float tt = g_T[idx];
    float d  = (float)g_deg[n];
    g_Z[(size_t)n * 256 + c]       = d * s;
    g_Z[(size_t)n * 256 + 128 + c] = (d - 1.0f) * s + tt;
}

// ---------------- generic 128x128 fp32 GEMM tile ----------------
// MODE 0: Out = A@W                         (node GEMMs)
// MODE 1: Out = A@W + P[other] + Q[node], accumulate stat1   (GEMM1 -> Y)
// MODE 2: Out = relu(bn1(A))@W, accumulate stat2             (GEMM2 -> d_out)
template<int KDIM, int OUTW, int MODE>
__global__ void __launch_bounds__(256, 2)
gemm_tile(const float* __restrict__ Amat, const float* __restrict__ Wmat,
          float* __restrict__ Out, const int* __restrict__ ei)
{
    __shared__ __align__(16) float As[8][132];
    __shared__ __align__(16) float Bs[8][132];
    __shared__ int   snode[128];
    __shared__ int   soth[128];
    __shared__ float s_sc[256];
    __shared__ float s_sh[256];

    const int t  = threadIdx.x;
    const int tx = t & 15;
    const int ty = t >> 4;
    const int row0 = blockIdx.x * 128;
    const int col0 = blockIdx.y * 128;

    if (MODE == 1 && t < 128) {
        int r = row0 + t;
        snode[t] = ei[r];
        soth[t]  = ei[r ^ 1];
    }
    if (MODE == 2 && t < KDIM) {
        s_sc[t] = g_sc1[t];
        s_sh[t] = g_sh1[t];
    }
    __syncthreads();

    float acc[8][8];
    #pragma unroll
    for (int i = 0; i < 8; i++)
        #pragma unroll
        for (int j = 0; j < 8; j++) acc[i][j] = 0.0f;

    const int m_l = t >> 1;
    const int k4  = (t & 1) * 4;
    const int kb  = t >> 5;
    const int n4  = (t & 31) * 4;

    const float* aptr = Amat + (size_t)(row0 + m_l) * KDIM + k4;
    const float* bptr = Wmat + (size_t)kb * OUTW + col0 + n4;

    for (int kt = 0; kt < KDIM; kt += 8) {
        float4 av = *(const float4*)(aptr + kt);
        if (MODE == 2) {
            int kk = kt + k4;
            av.x = fmaxf(fmaf(av.x, s_sc[kk + 0], s_sh[kk + 0]), 0.0f);
            av.y = fmaxf(fmaf(av.y, s_sc[kk + 1], s_sh[kk + 1]), 0.0f);
            av.z = fmaxf(fmaf(av.z, s_sc[kk + 2], s_sh[kk + 2]), 0.0f);
            av.w = fmaxf(fmaf(av.w, s_sc[kk + 3], s_sh[kk + 3]), 0.0f);
        }
        As[k4 + 0][m_l] = av.x;
        As[k4 + 1][m_l] = av.y;
        As[k4 + 2][m_l] = av.z;
        As[k4 + 3][m_l] = av.w;
        *(float4*)&Bs[kb][n4] = *(const float4*)(bptr + (size_t)kt * OUTW);
        __syncthreads();

        #pragma unroll
        for (int k = 0; k < 8; k++) {
            float a[8], b[8];
            *(float4*)(a)     = *(const float4*)&As[k][ty * 8];
            *(float4*)(a + 4) = *(const float4*)&As[k][ty * 8 + 4];
            *(float4*)(b)     = *(const float4*)&Bs[k][tx * 8];
            *(float4*)(b + 4) = *(const float4*)&Bs[k][tx * 8 + 4];
            #pragma unroll
            for (int i = 0; i < 8; i++)
                #pragma unroll
                for (int j = 0; j < 8; j++)
                    acc[i][j] = fmaf(a[i], b[j], acc[i][j]);
        }
        __syncthreads();
    }

    // ---------------- epilogue ----------------
    float cs[8], cq[8];
    #pragma unroll
    for (int j = 0; j < 8; j++) { cs[j] = 0.0f; cq[j] = 0.0f; }

    #pragma unroll
    for (int i = 0; i < 8; i++) {
        int rloc = ty * 8 + i;
        float v[8];
        #pragma unroll
        for (int j = 0; j < 8; j++) v[j] = acc[i][j];

        if (MODE == 1) {
            int nr = snode[rloc], orr = soth[rloc];
            const float4* Pp = (const float4*)&g_P[(size_t)orr * 256 + col0 + tx * 8];
            const float4* Qp = (const float4*)&g_Q[(size_t)nr  * 256 + col0 + tx * 8];
            float4 p0 = Pp[0], p1 = Pp[1], q0 = Qp[0], q1 = Qp[1];
            v[0] += p0.x + q0.x; v[1] += p0.y + q0.y; v[2] += p0.z + q0.z; v[3] += p0.w + q0.w;
            v[4] += p1.x + q1.x; v[5] += p1.y + q1.y; v[6] += p1.z + q1.z; v[7] += p1.w + q1.w;
        }
        if (MODE >= 1) {
            #pragma unroll
            for (int j = 0; j < 8; j++) { cs[j] += v[j]; cq[j] += v[j] * v[j]; }
        }
        float* orow = Out + (size_t)(row0 + rloc) * OUTW + col0 + tx * 8;
        *(float4*)(orow)     = make_float4(v[0], v[1], v[2], v[3]);
        *(float4*)(orow + 4) = make_float4(v[4], v[5], v[6], v[7]);
    }

    if (MODE >= 1) {
        __syncthreads();
        float* csum = &As[0][0];     // reuse smem (>=256 floats)
        float* csq  = csum + 128;
        if (t < 128) { csum[t] = 0.0f; csq[t] = 0.0f; }
        __syncthreads();
        #pragma unroll
        for (int j = 0; j < 8; j++) {
            atomicAdd(&csum[tx * 8 + j], cs[j]);
            atomicAdd(&csq[tx * 8 + j],  cq[j]);
        }
        __syncthreads();
        if (t < 128) {
            float* stat = (MODE == 1) ? g_stat1 : g_stat2;
            int half    = (MODE == 1) ? 256 : 128;
            atomicAdd(&stat[col0 + t],        csum[t]);
            atomicAdd(&stat[half + col0 + t], csq[t]);
        }
    }
}

// ---------------- BN finalize ----------------
__global__ void finalize1(const float* __restrict__ g, const float* __restrict__ b) {
    int c = threadIdx.x;   // 256
    float inv = 1.0f / (float)ROWSZ;
    float m   = g_stat1[c] * inv;
    float var = g_stat1[256 + c] * inv - m * m;
    float is  = rsqrtf(var + 1e-5f);
    g_sc1[c] = g[c] * is;
    g_sh1[c] = b[c] - m * is * g[c];
}

__global__ void finalize2(const float* __restrict__ g, const float* __restrict__ b) {
    int c = threadIdx.x;   // 128
    float inv = 1.0f / (float)ROWSZ;
    float m   = g_stat2[c] * inv;
    float var = g_stat2[128 + c] * inv - m * m;
    float is  = rsqrtf(var + 1e-5f);
    g_sc2[c] = g[c] * is;
    g_sh2[c] = b[c] - m * is * g[c];
}

// ---------------- final BN2 + ReLU in place on d_out ----------------
__global__ void bn2_relu(float* __restrict__ out) {
    int idx = blockIdx.x * blockDim.x + threadIdx.x;   // ROWSZ*32 float4s
    float4 v = ((float4*)out)[idx];
    int c = (idx & 31) * 4;
    v.x = fmaxf(fmaf(v.x, g_sc2[c + 0], g_sh2[c + 0]), 0.0f);
    v.y = fmaxf(fmaf(v.y, g_sc2[c + 1], g_sh2[c + 1]), 0.0f);
    v.z = fmaxf(fmaf(v.z, g_sc2[c + 2], g_sh2[c + 2]), 0.0f);
    v.w = fmaxf(fmaf(v.w, g_sc2[c + 3], g_sh2[c + 3]), 0.0f);
    ((float4*)out)[idx] = v;
}

extern "C" void kernel_launch(void* const* d_in, const int* in_sizes, int n_in,
                              void* d_out, int out_size)
{
    const float* x  = (const float*)d_in[0];
    const float* w1 = (const float*)d_in[1];
    const float* g1 = (const float*)d_in[2];
    const float* b1 = (const float*)d_in[3];
    const float* w2 = (const float*)d_in[4];
    const float* g2 = (const float*)d_in[5];
    const float* b2 = (const float*)d_in[6];
    const int*   ei = (const int*)d_in[7];
    float* out = (float*)d_out;

    void *pS, *pT, *pdeg, *pZ, *pP, *pQ, *pY, *pA, *pBw, *pCw, *ps1, *ps2;
    cudaGetSymbolAddress(&pS,  g_S);
    cudaGetSymbolAddress(&pT,  g_T);
    cudaGetSymbolAddress(&pdeg, g_deg);
    cudaGetSymbolAddress(&pZ,  g_Z);
    cudaGetSymbolAddress(&pP,  g_P);
    cudaGetSymbolAddress(&pQ,  g_Q);
    cudaGetSymbolAddress(&pY,  g_Y);
    cudaGetSymbolAddress(&pA,  g_A);
    cudaGetSymbolAddress(&pBw, g_Bw);
    cudaGetSymbolAddress(&pCw, g_Cw);
    cudaGetSymbolAddress(&ps1, g_stat1);
    cudaGetSymbolAddress(&ps2, g_stat2);

    cudaMemsetAsync(pS,   0, sizeof(g_S));
    cudaMemsetAsync(pT,   0, sizeof(g_T));
    cudaMemsetAsync(pdeg, 0, sizeof(g_deg));
    cudaMemsetAsync(ps1,  0, sizeof(g_stat1));
    cudaMemsetAsync(ps2,  0, sizeof(g_stat2));

    prep_w<<<256, 256>>>(w1);
    edge_accum<<<(EDGES + 7) / 8, 256>>>(x, ei);
    build_Z<<<NPAD * CDIM / 256, 256>>>();

    // node GEMMs: P = S@Bw, Q = Z@Cw
    gemm_tile<128, 256, 0><<<dim3(NPAD / 128, 2), 256>>>((const float*)pS, (const float*)pBw, (float*)pP, nullptr);
    gemm_tile<256, 256, 0><<<dim3(NPAD / 128, 2), 256>>>((const float*)pZ, (const float*)pCw, (float*)pQ, nullptr);

    // GEMM1: Y = x@A + P[other] + Q[node], stats1
    gemm_tile<128, 256, 1><<<dim3(ROWSZ / 128, 2), 256>>>(x, (const float*)pA, (float*)pY, ei);
    finalize1<<<1, 256>>>(g1, b1);

    // GEMM2: d_out = relu(bn1(Y))@w2 (pre-BN2), stats2
    gemm_tile<256, 128, 2><<<dim3(ROWSZ / 128, 1), 256>>>((const float*)pY, w2, out, nullptr);
    finalize2<<<1, 128>>>(g2, b2);

    bn2_relu<<<ROWSZ * 32 / 256, 256>>>(out);
}

// round 3
// speedup vs baseline: 1.0025x; 1.0025x over previous
#include <cuda_runtime.h>

#define EDGES 200000
#define ROWSZ 400000
#define CDIM  128
#define NPAD  50048      // 391*128, padded node count

// ---------------- scratch (static device allocations) ----------------
__device__ float g_S[NPAD * CDIM];          // segment sum of x
__device__ float g_T[NPAD * CDIM];          // segment sum of pair sums
__device__ int   g_deg[NPAD];               // rows per node
__device__ float g_Z[NPAD * 256];           // [deg*S, (deg-1)*S + T]
__device__ float g_P[NPAD * 256];           // S @ Bw
__device__ float g_Q[NPAD * 256];           // Z @ Cw
__device__ float g_Y[102400000];            // pre-BN1 activations [2E, 256]
__device__ float g_A[CDIM * 256];           // W0 + Wm2
__device__ float g_Bw[CDIM * 256];          // Wm1 + Wm2
__device__ float g_Cw[256 * 256];           // Wl + Wm
__device__ float g_stat1[512];              // col sum / sumsq of Y
__device__ float g_stat2[256];              // col sum / sumsq of pre-BN2
__device__ float g_sc1[256], g_sh1[256];
__device__ float g_sc2[128], g_sh2[128];

// ---------------- weight folding ----------------
__global__ void prep_w(const float* __restrict__ w1) {
    int idx = blockIdx.x * blockDim.x + threadIdx.x;   // 65536
    int k = idx >> 8;
    int j = idx & 255;
    g_Cw[idx] = w1[(128 + k) * 256 + j] + w1[(384 + k) * 256 + j];
    if (k < 128) {
        g_A[idx]  = w1[k * 256 + j]         + w1[(512 + k) * 256 + j];
        g_Bw[idx] = w1[(384 + k) * 256 + j] + w1[(512 + k) * 256 + j];
    }
}

// ---------------- per-edge segment accumulation ----------------
__global__ void edge_accum(const float* __restrict__ x, const int* __restrict__ ei) {
    int gw   = (blockIdx.x * blockDim.x + threadIdx.x) >> 5;
    int lane = threadIdx.x & 31;
    if (gw >= EDGES) return;
    int n0 = ei[2 * gw], n1 = ei[2 * gw + 1];
    const float4* x4 = (const float4*)x;
    float4 a = x4[(size_t)(2 * gw) * 32 + lane];
    float4 b = x4[(size_t)(2 * gw) * 32 + 32 + lane];
    float4 p = make_float4(a.x + b.x, a.y + b.y, a.z + b.z, a.w + b.w);
    atomicAdd((float4*)&g_S[(size_t)n0 * CDIM + lane * 4], a);
    atomicAdd((float4*)&g_S[(size_t)n1 * CDIM + lane * 4], b);
    atomicAdd((float4*)&g_T[(size_t)n0 * CDIM + lane * 4], p);
    atomicAdd((float4*)&g_T[(size_t)n1 * CDIM + lane * 4], p);
    if (lane == 0) { atomicAdd(&g_deg[n0], 1); atomicAdd(&g_deg[n1], 1); }
}

// ---------------- build Z = [deg*S, (deg-1)*S + T] ----------------
__global__ void build_Z() {
    int idx = blockIdx.x * blockDim.x + threadIdx.x;   // NPAD*128
    int n = idx >> 7, c = idx & 127;
    float s  = g_S[idx];
    float tt = g_T[idx];
    float d  = (float)g_deg[n];
    g_Z[(size_t)n * 256 + c]       = d * s;
    g_Z[(size_t)n * 256 + 128 + c] = (d - 1.0f) * s + tt;
}

// ---------------- generic 128x128 fp32 GEMM tile ----------------
// MODE 0: Out = A@W                         (node GEMMs)
// MODE 1: Out = A@W + P[other] + Q[node], accumulate stat1   (GEMM1 -> Y)
// MODE 2: Out = relu(bn1(A))@W, accumulate stat2             (GEMM2 -> d_out)
template<int KDIM, int OUTW, int MODE>
__global__ void __launch_bounds__(256, 2)
gemm_tile(const float* __restrict__ Amat, const float* __restrict__ Wmat,
          float* __restrict__ Out, const int* __restrict__ ei)
{
    __shared__ __align__(16) float As[8][132];
    __shared__ __align__(16) float Bs[8][132];
    __shared__ int   snode[128];
    __shared__ int   soth[128];
    __shared__ float s_sc[256];
    __shared__ float s_sh[256];

    const int t  = threadIdx.x;
    const int tx = t & 15;
    const int ty = t >> 4;
    const int row0 = blockIdx.x * 128;
    const int col0 = blockIdx.y * 128;

    if (MODE == 1 && t < 128) {
        int r = row0 + t;
        snode[t] = ei[r];
        soth[t]  = ei[r ^ 1];
    }
    if (MODE == 2 && t < KDIM) {
        s_sc[t] = g_sc1[t];
        s_sh[t] = g_sh1[t];
    }
    __syncthreads();

    float acc[8][8];
    #pragma unroll
    for (int i = 0; i < 8; i++)
        #pragma unroll
        for (int j = 0; j < 8; j++) acc[i][j] = 0.0f;

    const int m_l = t >> 1;
    const int k4  = (t & 1) * 4;
    const int kb  = t >> 5;
    const int n4  = (t & 31) * 4;

    const float* aptr = Amat + (size_t)(row0 + m_l) * KDIM + k4;
    const float* bptr = Wmat + (size_t)kb * OUTW + col0 + n4;

    for (int kt = 0; kt < KDIM; kt += 8) {
        float4 av = *(const float4*)(aptr + kt);
        if (MODE == 2) {
            int kk = kt + k4;
            av.x = fmaxf(fmaf(av.x, s_sc[kk + 0], s_sh[kk + 0]), 0.0f);
            av.y = fmaxf(fmaf(av.y, s_sc[kk + 1], s_sh[kk + 1]), 0.0f);
            av.z = fmaxf(fmaf(av.z, s_sc[kk + 2], s_sh[kk + 2]), 0.0f);
            av.w = fmaxf(fmaf(av.w, s_sc[kk + 3], s_sh[kk + 3]), 0.0f);
        }
        As[k4 + 0][m_l] = av.x;
        As[k4 + 1][m_l] = av.y;
        As[k4 + 2][m_l] = av.z;
        As[k4 + 3][m_l] = av.w;
        *(float4*)&Bs[kb][n4] = *(const float4*)(bptr + (size_t)kt * OUTW);
        __syncthreads();

        #pragma unroll
        for (int k = 0; k < 8; k++) {
            float a[8], b[8];
            *(float4*)(a)     = *(const float4*)&As[k][ty * 8];
            *(float4*)(a + 4) = *(const float4*)&As[k][ty * 8 + 4];
            *(float4*)(b)     = *(const float4*)&Bs[k][tx * 8];
            *(float4*)(b + 4) = *(const float4*)&Bs[k][tx * 8 + 4];
            #pragma unroll
            for (int i = 0; i < 8; i++)
                #pragma unroll
                for (int j = 0; j < 8; j++)
                    acc[i][j] = fmaf(a[i], b[j], acc[i][j]);
        }
        __syncthreads();
    }

    // ---------------- epilogue ----------------
    float cs[8], cq[8];
    #pragma unroll
    for (int j = 0; j < 8; j++) { cs[j] = 0.0f; cq[j] = 0.0f; }

    #pragma unroll
    for (int i = 0; i < 8; i++) {
        int rloc = ty * 8 + i;
        float v[8];
        #pragma unroll
        for (int j = 0; j < 8; j++) v[j] = acc[i][j];

        if (MODE == 1) {
            int nr = snode[rloc], orr = soth[rloc];
            const float4* Pp = (const float4*)&g_P[(size_t)orr * 256 + col0 + tx * 8];
            const float4* Qp = (const float4*)&g_Q[(size_t)nr  * 256 + col0 + tx * 8];
            float4 p0 = Pp[0], p1 = Pp[1], q0 = Qp[0], q1 = Qp[1];
            v[0] += p0.x + q0.x; v[1] += p0.y + q0.y; v[2] += p0.z + q0.z; v[3] += p0.w + q0.w;
            v[4] += p1.x + q1.x; v[5] += p1.y + q1.y; v[6] += p1.z + q1.z; v[7] += p1.w + q1.w;
        }
        if (MODE >= 1) {
            #pragma unroll
            for (int j = 0; j < 8; j++) { cs[j] += v[j]; cq[j] += v[j] * v[j]; }
        }
        float* orow = Out + (size_t)(row0 + rloc) * OUTW + col0 + tx * 8;
        *(float4*)(orow)     = make_float4(v[0], v[1], v[2], v[3]);
        *(float4*)(orow + 4) = make_float4(v[4], v[5], v[6], v[7]);
    }

    if (MODE >= 1) {
        __syncthreads();
        float* csum = &As[0][0];     // reuse smem (>=256 floats)
        float* csq  = csum + 128;
        if (t < 128) { csum[t] = 0.0f; csq[t] = 0.0f; }
        __syncthreads();
        #pragma unroll
        for (int j = 0; j < 8; j++) {
            atomicAdd(&csum[tx * 8 + j], cs[j]);
            atomicAdd(&csq[tx * 8 + j],  cq[j]);
        }
        __syncthreads();
        if (t < 128) {
            float* stat = (MODE == 1) ? g_stat1 : g_stat2;
            int half    = (MODE == 1) ? 256 : 128;
            atomicAdd(&stat[col0 + t],        csum[t]);
            atomicAdd(&stat[half + col0 + t], csq[t]);
        }
    }
}

// ---------------- BN finalize ----------------
__global__ void finalize1(const float* __restrict__ g, const float* __restrict__ b) {
    int c = threadIdx.x;   // 256
    float inv = 1.0f / (float)ROWSZ;
    float m   = g_stat1[c] * inv;
    float var = g_stat1[256 + c] * inv - m * m;
    float is  = rsqrtf(var + 1e-5f);
    g_sc1[c] = g[c] * is;
    g_sh1[c] = b[c] - m * is * g[c];
}

__global__ void finalize2(const float* __restrict__ g, const float* __restrict__ b) {
    int c = threadIdx.x;   // 128
    float inv = 1.0f / (float)ROWSZ;
    float m   = g_stat2[c] * inv;
    float var = g_stat2[128 + c] * inv - m * m;
    float is  = rsqrtf(var + 1e-5f);
    g_sc2[c] = g[c] * is;
    g_sh2[c] = b[c] - m * is * g[c];
}

// ---------------- final BN2 + ReLU in place on d_out ----------------
__global__ void bn2_relu(float* __restrict__ out) {
    int idx = blockIdx.x * blockDim.x + threadIdx.x;   // ROWSZ*32 float4s
    float4 v = ((float4*)out)[idx];
    int c = (idx & 31) * 4;
    v.x = fmaxf(fmaf(v.x, g_sc2[c + 0], g_sh2[c + 0]), 0.0f);
    v.y = fmaxf(fmaf(v.y, g_sc2[c + 1], g_sh2[c + 1]), 0.0f);
    v.z = fmaxf(fmaf(v.z, g_sc2[c + 2], g_sh2[c + 2]), 0.0f);
    v.w = fmaxf(fmaf(v.w, g_sc2[c + 3], g_sh2[c + 3]), 0.0f);
    ((float4*)out)[idx] = v;
}

extern "C" void kernel_launch(void* const* d_in, const int* in_sizes, int n_in,
                              void* d_out, int out_size)
{
    const float* x  = (const float*)d_in[0];
    const float* w1 = (const float*)d_in[1];
    const float* g1 = (const float*)d_in[2];
    const float* b1 = (const float*)d_in[3];
    const float* w2 = (const float*)d_in[4];
    const float* g2 = (const float*)d_in[5];
    const float* b2 = (const float*)d_in[6];
    const int*   ei = (const int*)d_in[7];
    float* out = (float*)d_out;

    void *pS, *pT, *pdeg, *pZ, *pP, *pQ, *pY, *pA, *pBw, *pCw, *ps1, *ps2;
    cudaGetSymbolAddress(&pS,  g_S);
    cudaGetSymbolAddress(&pT,  g_T);
    cudaGetSymbolAddress(&pdeg, g_deg);
    cudaGetSymbolAddress(&pZ,  g_Z);
    cudaGetSymbolAddress(&pP,  g_P);
    cudaGetSymbolAddress(&pQ,  g_Q);
    cudaGetSymbolAddress(&pY,  g_Y);
    cudaGetSymbolAddress(&pA,  g_A);
    cudaGetSymbolAddress(&pBw, g_Bw);
    cudaGetSymbolAddress(&pCw, g_Cw);
    cudaGetSymbolAddress(&ps1, g_stat1);
    cudaGetSymbolAddress(&ps2, g_stat2);

    cudaMemsetAsync(pS,   0, sizeof(g_S));
    cudaMemsetAsync(pT,   0, sizeof(g_T));
    cudaMemsetAsync(pdeg, 0, sizeof(g_deg));
    cudaMemsetAsync(ps1,  0, sizeof(g_stat1));
    cudaMemsetAsync(ps2,  0, sizeof(g_stat2));

    prep_w<<<256, 256>>>(w1);
    edge_accum<<<(EDGES + 7) / 8, 256>>>(x, ei);
    build_Z<<<NPAD * CDIM / 256, 256>>>();

    // node GEMMs: P = S@Bw, Q = Z@Cw
    gemm_tile<128, 256, 0><<<dim3(NPAD / 128, 2), 256>>>((const float*)pS, (const float*)pBw, (float*)pP, nullptr);
    gemm_tile<256, 256, 0><<<dim3(NPAD / 128, 2), 256>>>((const float*)pZ, (const float*)pCw, (float*)pQ, nullptr);

    // GEMM1: Y = x@A + P[other] + Q[node], stats1
    gemm_tile<128, 256, 1><<<dim3(ROWSZ / 128, 2), 256>>>(x, (const float*)pA, (float*)pY, ei);
    finalize1<<<1, 256>>>(g1, b1);

    // GEMM2: d_out = relu(bn1(Y))@w2 (pre-BN2), stats2
    gemm_tile<256, 128, 2><<<dim3(ROWSZ / 128, 1), 256>>>((const float*)pY, w2, out, nullptr);
    finalize2<<<1, 128>>>(g2, b2);

    bn2_relu<<<ROWSZ * 32 / 256, 256>>>(out);
}